// round 14
// baseline (speedup 1.0000x reference)
#include <cuda_runtime.h>

#define NN 4096
#define MM 32
#define LOG2F_ 0.693147180559945f

typedef unsigned long long u64;

// ---- scratch globals ----
__device__ float g_pre[NN * 256];  // ielin(feat) per node
__device__ float g_acc[NN * 704];  // coupling accumulators
__device__ float g_agg[NN * 256];  // post-w_a aggregate

__device__ __forceinline__ float ssp(float x) {
    return fmaxf(x, 0.f) + __logf(1.f + __expf(-fabsf(x))) - LOG2F_;
}
__device__ __forceinline__ u64 pk2(float a, float b) {
    u64 r; asm("mov.b64 %0, {%1, %2};" : "=l"(r) : "f"(a), "f"(b)); return r;
}
__device__ __forceinline__ void upk2(u64 v, float& a, float& b) {
    asm("mov.b64 {%0, %1}, %2;" : "=f"(a), "=f"(b) : "l"(v));
}
__device__ __forceinline__ u64 fma2_(u64 a, u64 b, u64 c) {
    u64 r; asm("fma.rn.f32x2 %0, %1, %2, %3;" : "=l"(r) : "l"(a), "l"(b), "l"(c)); return r;
}

// ---- bf16 helpers ----
__device__ __forceinline__ unsigned pkbf(float lo, float hi) {
    unsigned r;
    asm("cvt.rn.bf16x2.f32 %0, %1, %2;" : "=r"(r) : "f"(hi), "f"(lo));
    return r;  // low 16 bits = bf16(lo), high = bf16(hi)
}
__device__ __forceinline__ void split2(float x, float y, unsigned& h, unsigned& l) {
    h = pkbf(x, y);
    float hx = __uint_as_float(h << 16);
    float hy = __uint_as_float(h & 0xFFFF0000u);
    l = pkbf(x - hx, y - hy);
}
__device__ __forceinline__ void mma16816(float* C, unsigned a0, unsigned a1,
                                         unsigned a2, unsigned a3,
                                         unsigned b0, unsigned b1) {
    asm volatile(
        "mma.sync.aligned.m16n8k16.row.col.f32.bf16.bf16.f32 "
        "{%0,%1,%2,%3}, {%4,%5,%6,%7}, {%8,%9}, {%0,%1,%2,%3};\n"
        : "+f"(C[0]), "+f"(C[1]), "+f"(C[2]), "+f"(C[3])
        : "r"(a0), "r"(a1), "r"(a2), "r"(a3), "r"(b0), "r"(b1));
}

// ============================================================
// K1: g_pre = ielin(feat, wp0, wp1). 8 nodes/block, grid 512. Split-k.
// ============================================================
#define KP_SMEM ((4096 + 4096 + 64 * 36) * 4)
__global__ void __launch_bounds__(256) k_pre(const float* __restrict__ feat,
                                             const float* __restrict__ wp0,
                                             const float* __restrict__ wp1) {
    extern __shared__ float sm[];
    float* sW0 = sm;
    float* sW1 = sm + 4096;
    float* sAt = sm + 8192;  // [k64][row32], stride 36
    int t = threadIdx.x;
    for (int i = t; i < 1024; i += 256) {
        ((float4*)sW0)[i] = ((const float4*)wp0)[i];
        ((float4*)sW1)[i] = ((const float4*)wp1)[i];
    }
    const float4* src = (const float4*)feat + blockIdx.x * 512;
#pragma unroll
    for (int jj = 0; jj < 2; jj++) {
        int idx = t + jj * 256;
        float4 v = src[idx];
        int d = idx * 4, r = d >> 6, k0 = d & 63;
        sAt[(k0 + 0) * 36 + r] = v.x;
        sAt[(k0 + 1) * 36 + r] = v.y;
        sAt[(k0 + 2) * 36 + r] = v.z;
        sAt[(k0 + 3) * 36 + r] = v.w;
    }
    __syncthreads();
    int rg = t >> 5, c0 = (t & 31) * 2;
    u64 a0L = pk2(0.f, 0.f), a1L = a0L, a2L = a0L, a3L = a0L;
    u64 a0H = a0L, a1H = a0L, a2H = a0L, a3H = a0L;
#pragma unroll 4
    for (int k = 0; k < 32; k++) {
        float4 aL = *(const float4*)(sAt + k * 36 + rg * 4);
        float4 aH = *(const float4*)(sAt + (k + 32) * 36 + rg * 4);
        u64 w0L = *(const u64*)(sW0 + k * 64 + c0);
        u64 w1L = *(const u64*)(sW1 + k * 64 + c0);
        u64 w0H = *(const u64*)(sW0 + (k + 32) * 64 + c0);
        u64 w1H = *(const u64*)(sW1 + (k + 32) * 64 + c0);
        a0L = fma2_(pk2(aL.x, aL.x), w0L, a0L);
        a0H = fma2_(pk2(aH.x, aH.x), w0H, a0H);
        a1L = fma2_(pk2(aL.y, aL.y), w1L, a1L);
        a1H = fma2_(pk2(aH.y, aH.y), w1H, a1H);
        a2L = fma2_(pk2(aL.z, aL.z), w1L, a2L);
        a2H = fma2_(pk2(aH.z, aH.z), w1H, a2H);
        a3L = fma2_(pk2(aL.w, aL.w), w1L, a3L);
        a3H = fma2_(pk2(aH.w, aH.w), w1H, a3H);
    }
    int node = blockIdx.x * 8 + rg;
    float xa, xb, ya, yb;
    upk2(a0L, xa, xb); upk2(a0H, ya, yb);
    *(float2*)(g_pre + node * 256 + c0) = make_float2(xa + ya, xb + yb);
    upk2(a1L, xa, xb); upk2(a1H, ya, yb);
    *(float2*)(g_pre + node * 256 + 64 + c0) = make_float2(xa + ya, xb + yb);
    upk2(a2L, xa, xb); upk2(a2H, ya, yb);
    *(float2*)(g_pre + node * 256 + 128 + c0) = make_float2(xa + ya, xb + yb);
    upk2(a3L, xa, xb); upk2(a3H, ya, yb);
    *(float2*)(g_pre + node * 256 + 192 + c0) = make_float2(xa + ya, xb + yb);
#if __CUDA_ARCH__ >= 900
    cudaTriggerProgrammaticLaunchCompletion();
#endif
}

// ============================================================
// K2: fused edge kernel (filters + coupling). warp = node, 8 warps/block.
// ============================================================
#define KE_WARPS 8
#define KE_PW (576 + 272 + 128)
#define KE_SMEM ((1024 + 4096 + KE_WARPS * KE_PW) * 4)

#define COUPLE(UE, A0, AY, AZ, AX, F) do { \
    float fa, fb; upk2(F, fa, fb); \
    float uy = UE.x, uz = UE.y, ux = UE.z; \
    float sa = AY.x * uy + AZ.x * uz + AX.x * ux; \
    float sb = AY.y * uy + AZ.y * uz + AX.y * ux; \
    float t0a = A0.x * fa, t0b = A0.y * fb; \
    S0a += t0a;       S0b += t0b; \
    S1a += sa * fa;   S1b += sb * fb; \
    U0a += uy * t0a;  U0b += uy * t0b; \
    U1a += uz * t0a;  U1b += uz * t0b; \
    U2a += ux * t0a;  U2b += ux * t0b; \
    P0a += AY.x * fa; P0b += AY.y * fb; \
    P1a += AZ.x * fa; P1b += AZ.y * fb; \
    P2a += AX.x * fa; P2b += AX.y * fb; \
    float cya = AZ.x * ux - AX.x * uz, cyb = AZ.y * ux - AX.y * uz; \
    float cza = AX.x * uy - AY.x * ux, czb = AX.y * uy - AY.y * ux; \
    float cxa = AY.x * uz - AZ.x * uy, cxb = AY.y * uz - AZ.y * uy; \
    Q0a += cya * fa;  Q0b += cyb * fb; \
    Q1a += cza * fa;  Q1b += czb * fb; \
    Q2a += cxa * fa;  Q2b += cxb * fb; \
} while (0)

__global__ void __launch_bounds__(256) k_edge(const float* __restrict__ xyz,
                                              const float* __restrict__ wf1,
                                              const float* __restrict__ wf2,
                                              const int* __restrict__ src,
                                              const int* __restrict__ emask) {
    extern __shared__ float sm[];
    float* sW1 = sm;
    float* sW2 = sm + 1024;
    int t = threadIdx.x, w = t >> 5, lane = t & 31;
    for (int i = t; i < 256; i += 256) ((float4*)sW1)[i] = ((const float4*)wf1)[i];
    for (int i = t; i < 1024; i += 256) ((float4*)sW2)[i] = ((const float4*)wf2)[i];
    float* base = sm + 5120 + w * KE_PW;
    float* sRB = base;
    float* sH = base + 576;
    float4* s_u = (float4*)(base + 848);
    __syncthreads();

    int node = blockIdx.x * KE_WARPS + w;
    s_u[lane] = make_float4(0.f, 0.f, 0.f, __int_as_float(node));
    __syncwarp();
    int eid = node * MM + lane;
    int mk = emask[eid];
    int j = src[eid];
    float nx = xyz[node * 3], ny = xyz[node * 3 + 1], nz = xyz[node * 3 + 2];
    float rx = xyz[j * 3] - nx, ry = xyz[j * 3 + 1] - ny, rz = xyz[j * 3 + 2] - nz;
    float d2 = rx * rx + ry * ry + rz * rz;
    float invd = rsqrtf(d2);
    float x = d2 * invd * 0.2f;
    bool act = (mk != 0) && (x < 1.f);
    unsigned actmask = __ballot_sync(0xffffffffu, act);
    int nact = __popc(actmask);
    int rank = __popc(actmask & ((1u << lane) - 1u));
    if (act) {
        float x3 = x * x * x;
        float env = 1.f + x3 * (-10.f + x * (15.f - 6.f * x));
        float scale = env * invd;
        s_u[rank] = make_float4(ry * invd, rz * invd, rx * invd, __int_as_float(j));
#pragma unroll
        for (int q = 0; q < 16; q++) sRB[q * 36 + rank] = __sinf(x * (float)q) * scale;
    }
    __syncwarp();

#if __CUDA_ARCH__ >= 900
    cudaGridDependencySynchronize();
#endif

    int c0 = lane * 2;
    float S0a = 0, S0b = 0, S1a = 0, S1b = 0;
    float U0a = 0, U0b = 0, U1a = 0, U1b = 0, U2a = 0, U2b = 0;
    float P0a = 0, P0b = 0, P1a = 0, P1b = 0, P2a = 0, P2b = 0;
    float Q0a = 0, Q0b = 0, Q1a = 0, Q1b = 0, Q2a = 0, Q2b = 0;

    for (int r0 = 0; r0 < nact; r0 += 4) {
        float4 ue0 = s_u[r0], ue1 = s_u[r0 + 1], ue2 = s_u[r0 + 2], ue3 = s_u[r0 + 3];
        const float* p0 = g_pre + __float_as_int(ue0.w) * 256 + c0;
        const float* p1 = g_pre + __float_as_int(ue1.w) * 256 + c0;
        const float* p2 = g_pre + __float_as_int(ue2.w) * 256 + c0;
        const float* p3 = g_pre + __float_as_int(ue3.w) * 256 + c0;
        float2 A00 = *(const float2*)(p0), A0y = *(const float2*)(p0 + 64),
               A0z = *(const float2*)(p0 + 128), A0x = *(const float2*)(p0 + 192);
        float2 B00 = *(const float2*)(p1), B0y = *(const float2*)(p1 + 64),
               B0z = *(const float2*)(p1 + 128), B0x = *(const float2*)(p1 + 192);
        float2 C00 = *(const float2*)(p2), C0y = *(const float2*)(p2 + 64),
               C0z = *(const float2*)(p2 + 128), C0x = *(const float2*)(p2 + 192);
        float2 D00 = *(const float2*)(p3), D0y = *(const float2*)(p3 + 64),
               D0z = *(const float2*)(p3 + 128), D0x = *(const float2*)(p3 + 192);

        u64 H0 = pk2(0.f, 0.f), H1 = H0, H2 = H0, H3 = H0;
#pragma unroll
        for (int q = 0; q < 16; q++) {
            float4 rb = *(const float4*)(sRB + q * 36 + r0);
            u64 wv = *(const u64*)(sW1 + q * 64 + c0);
            H0 = fma2_(pk2(rb.x, rb.x), wv, H0);
            H1 = fma2_(pk2(rb.y, rb.y), wv, H1);
            H2 = fma2_(pk2(rb.z, rb.z), wv, H2);
            H3 = fma2_(pk2(rb.w, rb.w), wv, H3);
        }
        {
            float a, b;
            upk2(H0, a, b); *(u64*)(sH + 0 * 68 + c0) = pk2(ssp(a), ssp(b));
            upk2(H1, a, b); *(u64*)(sH + 1 * 68 + c0) = pk2(ssp(a), ssp(b));
            upk2(H2, a, b); *(u64*)(sH + 2 * 68 + c0) = pk2(ssp(a), ssp(b));
            upk2(H3, a, b); *(u64*)(sH + 3 * 68 + c0) = pk2(ssp(a), ssp(b));
        }
        __syncwarp();

        u64 F0 = pk2(0.f, 0.f), F1 = F0, F2 = F0, F3 = F0;
#pragma unroll 4
        for (int kk = 0; kk < 64; kk += 4) {
            float4 h0 = *(const float4*)(sH + 0 * 68 + kk);
            float4 h1 = *(const float4*)(sH + 1 * 68 + kk);
            float4 h2 = *(const float4*)(sH + 2 * 68 + kk);
            float4 h3 = *(const float4*)(sH + 3 * 68 + kk);
            u64 w0 = *(const u64*)(sW2 + (kk + 0) * 64 + c0);
            u64 w1 = *(const u64*)(sW2 + (kk + 1) * 64 + c0);
            u64 w2 = *(const u64*)(sW2 + (kk + 2) * 64 + c0);
            u64 w3 = *(const u64*)(sW2 + (kk + 3) * 64 + c0);
            F0 = fma2_(pk2(h0.x, h0.x), w0, F0);
            F1 = fma2_(pk2(h1.x, h1.x), w0, F1);
            F2 = fma2_(pk2(h2.x, h2.x), w0, F2);
            F3 = fma2_(pk2(h3.x, h3.x), w0, F3);
            F0 = fma2_(pk2(h0.y, h0.y), w1, F0);
            F1 = fma2_(pk2(h1.y, h1.y), w1, F1);
            F2 = fma2_(pk2(h2.y, h2.y), w1, F2);
            F3 = fma2_(pk2(h3.y, h3.y), w1, F3);
            F0 = fma2_(pk2(h0.z, h0.z), w2, F0);
            F1 = fma2_(pk2(h1.z, h1.z), w2, F1);
            F2 = fma2_(pk2(h2.z, h2.z), w2, F2);
            F3 = fma2_(pk2(h3.z, h3.z), w2, F3);
            F0 = fma2_(pk2(h0.w, h0.w), w3, F0);
            F1 = fma2_(pk2(h1.w, h1.w), w3, F1);
            F2 = fma2_(pk2(h2.w, h2.w), w3, F2);
            F3 = fma2_(pk2(h3.w, h3.w), w3, F3);
        }
        if (r0 + 1 >= nact) F1 = pk2(0.f, 0.f);
        if (r0 + 2 >= nact) F2 = pk2(0.f, 0.f);
        if (r0 + 3 >= nact) F3 = pk2(0.f, 0.f);

        COUPLE(ue0, A00, A0y, A0z, A0x, F0);
        COUPLE(ue1, B00, B0y, B0z, B0x, F1);
        COUPLE(ue2, C00, C0y, C0z, C0x, F2);
        COUPLE(ue3, D00, D0y, D0z, D0x, F3);
        __syncwarp();
    }

    float* dst = g_acc + node * 704 + c0;
    *(float2*)(dst + 0)   = make_float2(S0a, S0b);
    *(float2*)(dst + 64)  = make_float2(S1a, S1b);
    *(float2*)(dst + 128) = make_float2(U0a, U0b);
    *(float2*)(dst + 192) = make_float2(U1a, U1b);
    *(float2*)(dst + 256) = make_float2(U2a, U2b);
    *(float2*)(dst + 320) = make_float2(P0a, P0b);
    *(float2*)(dst + 384) = make_float2(P1a, P1b);
    *(float2*)(dst + 448) = make_float2(P2a, P2b);
    *(float2*)(dst + 512) = make_float2(Q0a, Q0b);
    *(float2*)(dst + 576) = make_float2(Q1a, Q1b);
    *(float2*)(dst + 640) = make_float2(Q2a, Q2b);
#if __CUDA_ARCH__ >= 900
    cudaTriggerProgrammaticLaunchCompletion();
#endif
}

// ============================================================
// K3: w_a GEMMs via bf16-split mma.sync (m16n8k16).
//   Blocks [0,32): l0 rows = nodes (4096 x K128).
//   Blocks [32,128): l1 rows = (node,m) (12288 x K192, strided A).
//   Warp = 16-row tile x 64 cols. Weights pre-split hi/lo, transposed.
// ============================================================
#define KAG_SMEM (192 * 64 * 2 * 2)   // 48 KB (bf16 hi+lo, worst case K=192)
__global__ void __launch_bounds__(256) k_ag(const float* __restrict__ wa0,
                                            const float* __restrict__ wa1) {
    extern __shared__ float smf[];
    unsigned short* Whi = (unsigned short*)smf;
    int t = threadIdx.x, w = t >> 5, lane = t & 31;
    bool isl0 = blockIdx.x < 32;
    const float* W = isl0 ? wa0 : wa1;
    int K = isl0 ? 128 : 192;
    unsigned short* Wlo = Whi + K * 64;
    int nW = K * 64;
    for (int i = t; i < nW; i += 256) {
        int k = i >> 6, c = i & 63;
        float v = W[i];
        unsigned hp = pkbf(v, 0.f);
        unsigned short hb = (unsigned short)(hp & 0xFFFFu);
        float hf = __uint_as_float(((unsigned)hb) << 16);
        unsigned lp = pkbf(v - hf, 0.f);
        Whi[c * K + k] = hb;
        Wlo[c * K + k] = (unsigned short)(lp & 0xFFFFu);
    }
#if __CUDA_ARCH__ >= 900
    cudaGridDependencySynchronize();
#endif
    __syncthreads();

    int lq = lane >> 2, lr = lane & 3;
    int tile = (isl0 ? blockIdx.x : (blockIdx.x - 32)) * 8 + w;
    int R0 = tile * 16 + lq;
    int R1 = R0 + 8;
    int base0, base1;
    if (isl0) {
        base0 = R0 * 704;
        base1 = R1 * 704;
    } else {
        int n0 = R0 / 3, m0 = R0 - n0 * 3;
        int n1 = R1 / 3, m1 = R1 - n1 * 3;
        base0 = n0 * 704 + 128 + m0 * 64;
        base1 = n1 * 704 + 128 + m1 * 64;
    }
    float C[8][4];
#pragma unroll
    for (int i = 0; i < 8; i++) C[i][0] = C[i][1] = C[i][2] = C[i][3] = 0.f;

    int nks = K >> 4;
    for (int ks = 0; ks < nks; ks++) {
        int klin = ks * 16 + lr * 2;
        int off;
        if (isl0) {
            off = klin;
        } else {
            int s = ks >> 2;
            off = s * 192 + (ks & 3) * 16 + lr * 2;
        }
        float2 f00 = *(const float2*)(g_acc + base0 + off);
        float2 f01 = *(const float2*)(g_acc + base0 + off + 8);
        float2 f10 = *(const float2*)(g_acc + base1 + off);
        float2 f11 = *(const float2*)(g_acc + base1 + off + 8);
        unsigned a0h, a0l, a1h, a1l, a2h, a2l, a3h, a3l;
        split2(f00.x, f00.y, a0h, a0l);
        split2(f10.x, f10.y, a1h, a1l);
        split2(f01.x, f01.y, a2h, a2l);
        split2(f11.x, f11.y, a3h, a3l);
#pragma unroll
        for (int nt = 0; nt < 8; nt++) {
            int n = nt * 8 + lq;
            const unsigned short* ph = Whi + n * K + klin;
            const unsigned short* pl = Wlo + n * K + klin;
            unsigned b0 = *(const unsigned*)(ph);
            unsigned b1 = *(const unsigned*)(ph + 8);
            unsigned e0 = *(const unsigned*)(pl);
            unsigned e1 = *(const unsigned*)(pl + 8);
            mma16816(C[nt], a0h, a1h, a2h, a3h, b0, b1);
            mma16816(C[nt], a0l, a1l, a2l, a3l, b0, b1);
            mma16816(C[nt], a0h, a1h, a2h, a3h, e0, e1);
        }
    }

    if (isl0) {
#pragma unroll
        for (int nt = 0; nt < 8; nt++) {
            int c = nt * 8 + lr * 2;
            *(float2*)(g_agg + R0 * 256 + c) = make_float2(C[nt][0], C[nt][1]);
            *(float2*)(g_agg + R1 * 256 + c) = make_float2(C[nt][2], C[nt][3]);
        }
    } else {
        int n0 = R0 / 3, m0 = R0 - n0 * 3;
        int n1 = R1 / 3, m1 = R1 - n1 * 3;
#pragma unroll
        for (int nt = 0; nt < 8; nt++) {
            int c = nt * 8 + lr * 2;
            *(float2*)(g_agg + n0 * 256 + (m0 + 1) * 64 + c) = make_float2(C[nt][0], C[nt][1]);
            *(float2*)(g_agg + n1 * 256 + (m1 + 1) * 64 + c) = make_float2(C[nt][2], C[nt][3]);
        }
    }
#if __CUDA_ARCH__ >= 900
    cudaTriggerProgrammaticLaunchCompletion();
#endif
}

// ============================================================
// K4: gate + w_b ielin + residual. 8 nodes/block, grid 512. Split-k.
// ============================================================
#define KFN_SMEM ((4096 + 4096 + 2048 + 64 * 36) * 4)
__global__ void __launch_bounds__(256) k_fin(const float* __restrict__ feat,
                                             const float* __restrict__ wb0,
                                             const float* __restrict__ wb1,
                                             float* __restrict__ out) {
    extern __shared__ float sm[];
    float* sW0 = sm;
    float* sW1 = sm + 4096;
    float* sAg = sm + 8192;
    float* sAt = sm + 10240;
    int t = threadIdx.x;
    for (int i = t; i < 1024; i += 256) {
        ((float4*)sW0)[i] = ((const float4*)wb0)[i];
        ((float4*)sW1)[i] = ((const float4*)wb1)[i];
    }
#if __CUDA_ARCH__ >= 900
    cudaGridDependencySynchronize();
#endif
    int nodeBase = blockIdx.x * 8;
    for (int i = t; i < 512; i += 256)
        ((float4*)sAg)[i] = *((const float4*)(g_agg + nodeBase * 256) + i);
    __syncthreads();
    for (int i = t; i < 512; i += 256) {
        int nl = i >> 6, c = i & 63;
        const float* a = sAg + nl * 256;
        float a0 = a[c], v1 = a[64 + c], v2 = a[128 + c], v3 = a[192 + c];
        float gt0 = ssp(a0);
        float gt1 = ssp(sqrtf(v1 * v1 + v2 * v2 + v3 * v3 + 1e-12f));
        int row = nl * 4;
        sAt[c * 36 + row] = a0 * gt0;
        sAt[c * 36 + row + 1] = v1 * gt1;
        sAt[c * 36 + row + 2] = v2 * gt1;
        sAt[c * 36 + row + 3] = v3 * gt1;
    }
    __syncthreads();
    int rg = t >> 5, c0 = (t & 31) * 2;
    u64 a0L = pk2(0.f, 0.f), a1L = a0L, a2L = a0L, a3L = a0L;
    u64 a0H = a0L, a1H = a0L, a2H = a0L, a3H = a0L;
#pragma unroll 4
    for (int k = 0; k < 32; k++) {
        float4 aL = *(const float4*)(sAt + k * 36 + rg * 4);
        float4 aH = *(const float4*)(sAt + (k + 32) * 36 + rg * 4);
        u64 w0L = *(const u64*)(sW0 + k * 64 + c0);
        u64 w1L = *(const u64*)(sW1 + k * 64 + c0);
        u64 w0H = *(const u64*)(sW0 + (k + 32) * 64 + c0);
        u64 w1H = *(const u64*)(sW1 + (k + 32) * 64 + c0);
        a0L = fma2_(pk2(aL.x, aL.x), w0L, a0L);
        a0H = fma2_(pk2(aH.x, aH.x), w0H, a0H);
        a1L = fma2_(pk2(aL.y, aL.y), w1L, a1L);
        a1H = fma2_(pk2(aH.y, aH.y), w1H, a1H);
        a2L = fma2_(pk2(aL.z, aL.z), w1L, a2L);
        a2H = fma2_(pk2(aH.z, aH.z), w1H, a2H);
        a3L = fma2_(pk2(aL.w, aL.w), w1L, a3L);
        a3H = fma2_(pk2(aH.w, aH.w), w1H, a3H);
    }
    int node = nodeBase + rg;
    u64 avL[4] = {a0L, a1L, a2L, a3L};
    u64 avH[4] = {a0H, a1H, a2H, a3H};
#pragma unroll
    for (int jj = 0; jj < 4; jj++) {
        int idx = node * 256 + jj * 64 + c0;
        float2 fv = *(const float2*)(feat + idx);
        float oa, ob, pa, pb;
        upk2(avL[jj], oa, ob);
        upk2(avH[jj], pa, pb);
        *(float2*)(out + idx) = make_float2(fv.x + oa + pa, fv.y + ob + pb);
    }
}

// ============================================================
template <typename... Args>
static void launch_pdl(void (*kern)(Args...), int grid, int smem, Args... args) {
    cudaLaunchConfig_t cfg = {};
    cfg.gridDim = dim3(grid, 1, 1);
    cfg.blockDim = dim3(256, 1, 1);
    cfg.dynamicSmemBytes = (size_t)smem;
    cfg.stream = 0;
    cudaLaunchAttribute attr[1];
    attr[0].id = cudaLaunchAttributeProgrammaticStreamSerialization;
    attr[0].val.programmaticStreamSerializationAllowed = 1;
    cfg.attrs = attr;
    cfg.numAttrs = 1;
    cudaLaunchKernelEx(&cfg, kern, args...);
}

extern "C" void kernel_launch(void* const* d_in, const int* in_sizes, int n_in,
                              void* d_out, int out_size) {
    const float* xyz = (const float*)d_in[0];
    const float* feat = (const float*)d_in[1];
    const float* wf1 = (const float*)d_in[2];
    const float* wf2 = (const float*)d_in[3];
    const float* wp0 = (const float*)d_in[4];
    const float* wp1 = (const float*)d_in[5];
    const float* wa0 = (const float*)d_in[6];
    const float* wa1 = (const float*)d_in[7];
    const float* wb0 = (const float*)d_in[8];
    const float* wb1 = (const float*)d_in[9];
    const int* src = (const int*)d_in[10];
    const int* emask = (const int*)d_in[11];
    float* out = (float*)d_out;

    cudaFuncSetAttribute(k_pre, cudaFuncAttributeMaxDynamicSharedMemorySize, KP_SMEM);
    cudaFuncSetAttribute(k_edge, cudaFuncAttributeMaxDynamicSharedMemorySize, KE_SMEM);
    cudaFuncSetAttribute(k_ag, cudaFuncAttributeMaxDynamicSharedMemorySize, KAG_SMEM);
    cudaFuncSetAttribute(k_fin, cudaFuncAttributeMaxDynamicSharedMemorySize, KFN_SMEM);

    k_pre<<<512, 256, KP_SMEM>>>(feat, wp0, wp1);
    launch_pdl(k_edge, NN / KE_WARPS, KE_SMEM, xyz, wf1, wf2, src, emask);
    launch_pdl(k_ag, 128, KAG_SMEM, wa0, wa1);
    launch_pdl(k_fin, 512, KFN_SMEM, feat, wb0, wb1, out);
}

// round 15
// speedup vs baseline: 1.2904x; 1.2904x over previous
#include <cuda_runtime.h>

#define NN 4096
#define MM 32
#define LOG2F_ 0.693147180559945f

typedef unsigned long long u64;

// ---- scratch globals ----
__device__ float g_pre[NN * 256];  // ielin(feat) per node
__device__ float g_acc[NN * 704];  // coupling accumulators
__device__ float g_agg[NN * 256];  // post-w_a aggregate

__device__ __forceinline__ float ssp(float x) {
    return fmaxf(x, 0.f) + __logf(1.f + __expf(-fabsf(x))) - LOG2F_;
}
__device__ __forceinline__ u64 pk2(float a, float b) {
    u64 r; asm("mov.b64 %0, {%1, %2};" : "=l"(r) : "f"(a), "f"(b)); return r;
}
__device__ __forceinline__ void upk2(u64 v, float& a, float& b) {
    asm("mov.b64 {%0, %1}, %2;" : "=f"(a), "=f"(b) : "l"(v));
}
__device__ __forceinline__ u64 fma2_(u64 a, u64 b, u64 c) {
    u64 r; asm("fma.rn.f32x2 %0, %1, %2, %3;" : "=l"(r) : "l"(a), "l"(b), "l"(c)); return r;
}

// ============================================================
// K1: g_pre = ielin(feat, wp0, wp1). 8 nodes/block (32 rows), grid 512.
// ============================================================
#define KP_SMEM ((4096 + 4096 + 64 * 36) * 4)
__global__ void __launch_bounds__(256) k_pre(const float* __restrict__ feat,
                                             const float* __restrict__ wp0,
                                             const float* __restrict__ wp1) {
    extern __shared__ float sm[];
    float* sW0 = sm;
    float* sW1 = sm + 4096;
    float* sAt = sm + 8192;  // [k64][row32], stride 36
    int t = threadIdx.x;
    for (int i = t; i < 1024; i += 256) {
        ((float4*)sW0)[i] = ((const float4*)wp0)[i];
        ((float4*)sW1)[i] = ((const float4*)wp1)[i];
    }
    const float4* src = (const float4*)feat + blockIdx.x * 512;
#pragma unroll
    for (int jj = 0; jj < 2; jj++) {
        int idx = t + jj * 256;
        float4 v = src[idx];
        int d = idx * 4, r = d >> 6, k0 = d & 63;
        sAt[(k0 + 0) * 36 + r] = v.x;
        sAt[(k0 + 1) * 36 + r] = v.y;
        sAt[(k0 + 2) * 36 + r] = v.z;
        sAt[(k0 + 3) * 36 + r] = v.w;
    }
    __syncthreads();
    int rg = t >> 5, c0 = (t & 31) * 2;
    u64 acc0 = pk2(0.f, 0.f), acc1 = acc0, acc2 = acc0, acc3 = acc0;
#pragma unroll 4
    for (int k = 0; k < 64; k++) {
        float4 a = *(const float4*)(sAt + k * 36 + rg * 4);
        u64 w0 = *(const u64*)(sW0 + k * 64 + c0);
        u64 w1 = *(const u64*)(sW1 + k * 64 + c0);
        acc0 = fma2_(pk2(a.x, a.x), w0, acc0);
        acc1 = fma2_(pk2(a.y, a.y), w1, acc1);
        acc2 = fma2_(pk2(a.z, a.z), w1, acc2);
        acc3 = fma2_(pk2(a.w, a.w), w1, acc3);
    }
    int node = blockIdx.x * 8 + rg;
    *(u64*)(g_pre + node * 256 + c0) = acc0;
    *(u64*)(g_pre + node * 256 + 64 + c0) = acc1;
    *(u64*)(g_pre + node * 256 + 128 + c0) = acc2;
    *(u64*)(g_pre + node * 256 + 192 + c0) = acc3;
#if __CUDA_ARCH__ >= 900
    cudaTriggerProgrammaticLaunchCompletion();
#endif
}

// ============================================================
// K2: fused edge kernel (filters + coupling). warp = node.
//     4 warps/block (128 thr), grid 1024: finer load balance, more
//     resident blocks to backfill straggler warps.
// ============================================================
#define KE_WARPS 4
#define KE_PW (576 + 272 + 128)  // sRB[16][36] + sH[4][68] + s_u[32]f4
#define KE_SMEM ((1024 + 4096 + KE_WARPS * KE_PW) * 4)

#define COUPLE(UE, A0, AY, AZ, AX, F) do { \
    float fa, fb; upk2(F, fa, fb); \
    float uy = UE.x, uz = UE.y, ux = UE.z; \
    float sa = AY.x * uy + AZ.x * uz + AX.x * ux; \
    float sb = AY.y * uy + AZ.y * uz + AX.y * ux; \
    float t0a = A0.x * fa, t0b = A0.y * fb; \
    S0a += t0a;       S0b += t0b; \
    S1a += sa * fa;   S1b += sb * fb; \
    U0a += uy * t0a;  U0b += uy * t0b; \
    U1a += uz * t0a;  U1b += uz * t0b; \
    U2a += ux * t0a;  U2b += ux * t0b; \
    P0a += AY.x * fa; P0b += AY.y * fb; \
    P1a += AZ.x * fa; P1b += AZ.y * fb; \
    P2a += AX.x * fa; P2b += AX.y * fb; \
    float cya = AZ.x * ux - AX.x * uz, cyb = AZ.y * ux - AX.y * uz; \
    float cza = AX.x * uy - AY.x * ux, czb = AX.y * uy - AY.y * ux; \
    float cxa = AY.x * uz - AZ.x * uy, cxb = AY.y * uz - AZ.y * uy; \
    Q0a += cya * fa;  Q0b += cyb * fb; \
    Q1a += cza * fa;  Q1b += czb * fb; \
    Q2a += cxa * fa;  Q2b += cxb * fb; \
} while (0)

__global__ void __launch_bounds__(128) k_edge(const float* __restrict__ xyz,
                                              const float* __restrict__ wf1,
                                              const float* __restrict__ wf2,
                                              const int* __restrict__ src,
                                              const int* __restrict__ emask) {
    extern __shared__ float sm[];
    float* sW1 = sm;         // wf1 [16][64]
    float* sW2 = sm + 1024;  // wf2 [64][64]
    int t = threadIdx.x, w = t >> 5, lane = t & 31;
    for (int i = t; i < 256; i += 128) ((float4*)sW1)[i] = ((const float4*)wf1)[i];
    for (int i = t; i < 1024; i += 128) ((float4*)sW2)[i] = ((const float4*)wf2)[i];
    float* base = sm + 5120 + w * KE_PW;
    float* sRB = base;                   // [q16][36]
    float* sH = base + 576;              // [e4][68]
    float4* s_u = (float4*)(base + 848); // [32] (uy,uz,ux,j)
    __syncthreads();

    int node = blockIdx.x * KE_WARPS + w;
    // ---- phase A: lane = edge (inputs only; overlaps with k_pre via PDL) ----
    s_u[lane] = make_float4(0.f, 0.f, 0.f, __int_as_float(node));
    __syncwarp();
    int eid = node * MM + lane;
    int mk = emask[eid];
    int j = src[eid];
    float nx = xyz[node * 3], ny = xyz[node * 3 + 1], nz = xyz[node * 3 + 2];
    float rx = xyz[j * 3] - nx, ry = xyz[j * 3 + 1] - ny, rz = xyz[j * 3 + 2] - nz;
    float d2 = rx * rx + ry * ry + rz * rz;
    float invd = rsqrtf(d2);
    float x = d2 * invd * 0.2f;
    bool act = (mk != 0) && (x < 1.f);
    unsigned actmask = __ballot_sync(0xffffffffu, act);
    int nact = __popc(actmask);
    int rank = __popc(actmask & ((1u << lane) - 1u));
    if (act) {
        float x3 = x * x * x;
        float env = 1.f + x3 * (-10.f + x * (15.f - 6.f * x));
        float scale = env * invd;
        s_u[rank] = make_float4(ry * invd, rz * invd, rx * invd, __int_as_float(j));
#pragma unroll
        for (int q = 0; q < 16; q++) sRB[q * 36 + rank] = __sinf(x * (float)q) * scale;
    }
    __syncwarp();

#if __CUDA_ARCH__ >= 900
    cudaGridDependencySynchronize();   // g_pre must be complete past this point
#endif

    // ---- phase B: 4-edge tiles; lane = channel pair c0 ----
    int c0 = lane * 2;
    float S0a = 0, S0b = 0, S1a = 0, S1b = 0;
    float U0a = 0, U0b = 0, U1a = 0, U1b = 0, U2a = 0, U2b = 0;
    float P0a = 0, P0b = 0, P1a = 0, P1b = 0, P2a = 0, P2b = 0;
    float Q0a = 0, Q0b = 0, Q1a = 0, Q1b = 0, Q2a = 0, Q2b = 0;

    for (int r0 = 0; r0 < nact; r0 += 4) {
        float4 ue0 = s_u[r0], ue1 = s_u[r0 + 1], ue2 = s_u[r0 + 2], ue3 = s_u[r0 + 3];
        const float* p0 = g_pre + __float_as_int(ue0.w) * 256 + c0;
        const float* p1 = g_pre + __float_as_int(ue1.w) * 256 + c0;
        const float* p2 = g_pre + __float_as_int(ue2.w) * 256 + c0;
        const float* p3 = g_pre + __float_as_int(ue3.w) * 256 + c0;
        float2 A00 = *(const float2*)(p0), A0y = *(const float2*)(p0 + 64),
               A0z = *(const float2*)(p0 + 128), A0x = *(const float2*)(p0 + 192);
        float2 B00 = *(const float2*)(p1), B0y = *(const float2*)(p1 + 64),
               B0z = *(const float2*)(p1 + 128), B0x = *(const float2*)(p1 + 192);
        float2 C00 = *(const float2*)(p2), C0y = *(const float2*)(p2 + 64),
               C0z = *(const float2*)(p2 + 128), C0x = *(const float2*)(p2 + 192);
        float2 D00 = *(const float2*)(p3), D0y = *(const float2*)(p3 + 64),
               D0z = *(const float2*)(p3 + 128), D0x = *(const float2*)(p3 + 192);

        u64 H0 = pk2(0.f, 0.f), H1 = H0, H2 = H0, H3 = H0;
#pragma unroll
        for (int q = 0; q < 16; q++) {
            float4 rb = *(const float4*)(sRB + q * 36 + r0);
            u64 wv = *(const u64*)(sW1 + q * 64 + c0);
            H0 = fma2_(pk2(rb.x, rb.x), wv, H0);
            H1 = fma2_(pk2(rb.y, rb.y), wv, H1);
            H2 = fma2_(pk2(rb.z, rb.z), wv, H2);
            H3 = fma2_(pk2(rb.w, rb.w), wv, H3);
        }
        {
            float a, b;
            upk2(H0, a, b); *(u64*)(sH + 0 * 68 + c0) = pk2(ssp(a), ssp(b));
            upk2(H1, a, b); *(u64*)(sH + 1 * 68 + c0) = pk2(ssp(a), ssp(b));
            upk2(H2, a, b); *(u64*)(sH + 2 * 68 + c0) = pk2(ssp(a), ssp(b));
            upk2(H3, a, b); *(u64*)(sH + 3 * 68 + c0) = pk2(ssp(a), ssp(b));
        }
        __syncwarp();

        u64 F0 = pk2(0.f, 0.f), F1 = F0, F2 = F0, F3 = F0;
#pragma unroll 4
        for (int kk = 0; kk < 64; kk += 4) {
            float4 h0 = *(const float4*)(sH + 0 * 68 + kk);
            float4 h1 = *(const float4*)(sH + 1 * 68 + kk);
            float4 h2 = *(const float4*)(sH + 2 * 68 + kk);
            float4 h3 = *(const float4*)(sH + 3 * 68 + kk);
            u64 w0 = *(const u64*)(sW2 + (kk + 0) * 64 + c0);
            u64 w1 = *(const u64*)(sW2 + (kk + 1) * 64 + c0);
            u64 w2 = *(const u64*)(sW2 + (kk + 2) * 64 + c0);
            u64 w3 = *(const u64*)(sW2 + (kk + 3) * 64 + c0);
            F0 = fma2_(pk2(h0.x, h0.x), w0, F0);
            F1 = fma2_(pk2(h1.x, h1.x), w0, F1);
            F2 = fma2_(pk2(h2.x, h2.x), w0, F2);
            F3 = fma2_(pk2(h3.x, h3.x), w0, F3);
            F0 = fma2_(pk2(h0.y, h0.y), w1, F0);
            F1 = fma2_(pk2(h1.y, h1.y), w1, F1);
            F2 = fma2_(pk2(h2.y, h2.y), w1, F2);
            F3 = fma2_(pk2(h3.y, h3.y), w1, F3);
            F0 = fma2_(pk2(h0.z, h0.z), w2, F0);
            F1 = fma2_(pk2(h1.z, h1.z), w2, F1);
            F2 = fma2_(pk2(h2.z, h2.z), w2, F2);
            F3 = fma2_(pk2(h3.z, h3.z), w2, F3);
            F0 = fma2_(pk2(h0.w, h0.w), w3, F0);
            F1 = fma2_(pk2(h1.w, h1.w), w3, F1);
            F2 = fma2_(pk2(h2.w, h2.w), w3, F2);
            F3 = fma2_(pk2(h3.w, h3.w), w3, F3);
        }
        if (r0 + 1 >= nact) F1 = pk2(0.f, 0.f);
        if (r0 + 2 >= nact) F2 = pk2(0.f, 0.f);
        if (r0 + 3 >= nact) F3 = pk2(0.f, 0.f);

        COUPLE(ue0, A00, A0y, A0z, A0x, F0);
        COUPLE(ue1, B00, B0y, B0z, B0x, F1);
        COUPLE(ue2, C00, C0y, C0z, C0x, F2);
        COUPLE(ue3, D00, D0y, D0z, D0x, F3);
        __syncwarp();
    }

    float* dst = g_acc + node * 704 + c0;
    *(float2*)(dst + 0)   = make_float2(S0a, S0b);
    *(float2*)(dst + 64)  = make_float2(S1a, S1b);
    *(float2*)(dst + 128) = make_float2(U0a, U0b);
    *(float2*)(dst + 192) = make_float2(U1a, U1b);
    *(float2*)(dst + 256) = make_float2(U2a, U2b);
    *(float2*)(dst + 320) = make_float2(P0a, P0b);
    *(float2*)(dst + 384) = make_float2(P1a, P1b);
    *(float2*)(dst + 448) = make_float2(P2a, P2b);
    *(float2*)(dst + 512) = make_float2(Q0a, Q0b);
    *(float2*)(dst + 576) = make_float2(Q1a, Q1b);
    *(float2*)(dst + 640) = make_float2(Q2a, Q2b);
#if __CUDA_ARCH__ >= 900
    cudaTriggerProgrammaticLaunchCompletion();
#endif
}

// ============================================================
// K3: combined w_a GEMMs, ONE launch, warp = 2 nodes (interleaved ILP).
// ============================================================
#define KAG_SMEM (12288 * 4)
__global__ void __launch_bounds__(256) k_ag(const float* __restrict__ wa0,
                                            const float* __restrict__ wa1) {
    extern __shared__ float sW[];
    int t = threadIdx.x, w = t >> 5, c0 = (t & 31) * 2;
    if (blockIdx.x < 256) {
        for (int i = t; i < 2048; i += 256) ((float4*)sW)[i] = ((const float4*)wa0)[i];
#if __CUDA_ARCH__ >= 900
        cudaGridDependencySynchronize();
#endif
        __syncthreads();
        int n0 = blockIdx.x * 16 + w * 2;
        const float* A = g_acc + n0 * 704;
        const float* B = A + 704;
        u64 e0 = pk2(0.f, 0.f), e1 = e0, f0 = e0, f1 = e0;
#pragma unroll 4
        for (int kk = 0; kk < 64; kk += 4) {
            float4 a = *(const float4*)(A + kk);
            float4 a2 = *(const float4*)(A + 64 + kk);
            float4 b = *(const float4*)(B + kk);
            float4 b2 = *(const float4*)(B + 64 + kk);
            u64 w0 = *(const u64*)(sW + (kk + 0) * 64 + c0);
            u64 v0 = *(const u64*)(sW + (64 + kk + 0) * 64 + c0);
            u64 w1 = *(const u64*)(sW + (kk + 1) * 64 + c0);
            u64 v1 = *(const u64*)(sW + (64 + kk + 1) * 64 + c0);
            u64 w2 = *(const u64*)(sW + (kk + 2) * 64 + c0);
            u64 v2 = *(const u64*)(sW + (64 + kk + 2) * 64 + c0);
            u64 w3 = *(const u64*)(sW + (kk + 3) * 64 + c0);
            u64 v3 = *(const u64*)(sW + (64 + kk + 3) * 64 + c0);
            e0 = fma2_(pk2(a.x, a.x), w0, e0);
            f0 = fma2_(pk2(b.x, b.x), w0, f0);
            e1 = fma2_(pk2(a2.x, a2.x), v0, e1);
            f1 = fma2_(pk2(b2.x, b2.x), v0, f1);
            e0 = fma2_(pk2(a.y, a.y), w1, e0);
            f0 = fma2_(pk2(b.y, b.y), w1, f0);
            e1 = fma2_(pk2(a2.y, a2.y), v1, e1);
            f1 = fma2_(pk2(b2.y, b2.y), v1, f1);
            e0 = fma2_(pk2(a.z, a.z), w2, e0);
            f0 = fma2_(pk2(b.z, b.z), w2, f0);
            e1 = fma2_(pk2(a2.z, a2.z), v2, e1);
            f1 = fma2_(pk2(b2.z, b2.z), v2, f1);
            e0 = fma2_(pk2(a.w, a.w), w3, e0);
            f0 = fma2_(pk2(b.w, b.w), w3, f0);
            e1 = fma2_(pk2(a2.w, a2.w), v3, e1);
            f1 = fma2_(pk2(b2.w, b2.w), v3, f1);
        }
        float xa, xb, ya, yb;
        upk2(e0, xa, xb); upk2(e1, ya, yb);
        *(float2*)(g_agg + n0 * 256 + c0) = make_float2(xa + ya, xb + yb);
        upk2(f0, xa, xb); upk2(f1, ya, yb);
        *(float2*)(g_agg + (n0 + 1) * 256 + c0) = make_float2(xa + ya, xb + yb);
    } else {
        for (int i = t; i < 3072; i += 256) ((float4*)sW)[i] = ((const float4*)wa1)[i];
#if __CUDA_ARCH__ >= 900
        cudaGridDependencySynchronize();
#endif
        __syncthreads();
        int n0 = (blockIdx.x - 256) * 16 + w * 2;
        u64 m0 = pk2(0.f, 0.f), m1 = m0, m2 = m0;
        u64 q0 = m0, q1 = m0, q2 = m0;
#pragma unroll
        for (int s = 0; s < 3; s++) {
            const float* As = g_acc + n0 * 704 + 128 + s * 192;
            const float* Bs = As + 704;
            const float* ws = sW + s * 4096;
#pragma unroll 2
            for (int kk = 0; kk < 64; kk += 4) {
                float4 a0 = *(const float4*)(As + kk);
                float4 a1 = *(const float4*)(As + 64 + kk);
                float4 a2 = *(const float4*)(As + 128 + kk);
                float4 b0 = *(const float4*)(Bs + kk);
                float4 b1 = *(const float4*)(Bs + 64 + kk);
                float4 b2 = *(const float4*)(Bs + 128 + kk);
                u64 w0 = *(const u64*)(ws + (kk + 0) * 64 + c0);
                u64 w1 = *(const u64*)(ws + (kk + 1) * 64 + c0);
                u64 w2 = *(const u64*)(ws + (kk + 2) * 64 + c0);
                u64 w3 = *(const u64*)(ws + (kk + 3) * 64 + c0);
                m0 = fma2_(pk2(a0.x, a0.x), w0, m0);
                q0 = fma2_(pk2(b0.x, b0.x), w0, q0);
                m1 = fma2_(pk2(a1.x, a1.x), w0, m1);
                q1 = fma2_(pk2(b1.x, b1.x), w0, q1);
                m2 = fma2_(pk2(a2.x, a2.x), w0, m2);
                q2 = fma2_(pk2(b2.x, b2.x), w0, q2);
                m0 = fma2_(pk2(a0.y, a0.y), w1, m0);
                q0 = fma2_(pk2(b0.y, b0.y), w1, q0);
                m1 = fma2_(pk2(a1.y, a1.y), w1, m1);
                q1 = fma2_(pk2(b1.y, b1.y), w1, q1);
                m2 = fma2_(pk2(a2.y, a2.y), w1, m2);
                q2 = fma2_(pk2(b2.y, b2.y), w1, q2);
                m0 = fma2_(pk2(a0.z, a0.z), w2, m0);
                q0 = fma2_(pk2(b0.z, b0.z), w2, q0);
                m1 = fma2_(pk2(a1.z, a1.z), w2, m1);
                q1 = fma2_(pk2(b1.z, b1.z), w2, q1);
                m2 = fma2_(pk2(a2.z, a2.z), w2, m2);
                q2 = fma2_(pk2(b2.z, b2.z), w2, q2);
                m0 = fma2_(pk2(a0.w, a0.w), w3, m0);
                q0 = fma2_(pk2(b0.w, b0.w), w3, q0);
                m1 = fma2_(pk2(a1.w, a1.w), w3, m1);
                q1 = fma2_(pk2(b1.w, b1.w), w3, q1);
                m2 = fma2_(pk2(a2.w, a2.w), w3, m2);
                q2 = fma2_(pk2(b2.w, b2.w), w3, q2);
            }
        }
        *(u64*)(g_agg + n0 * 256 + 64 + c0) = m0;
        *(u64*)(g_agg + n0 * 256 + 128 + c0) = m1;
        *(u64*)(g_agg + n0 * 256 + 192 + c0) = m2;
        *(u64*)(g_agg + (n0 + 1) * 256 + 64 + c0) = q0;
        *(u64*)(g_agg + (n0 + 1) * 256 + 128 + c0) = q1;
        *(u64*)(g_agg + (n0 + 1) * 256 + 192 + c0) = q2;
    }
#if __CUDA_ARCH__ >= 900
    cudaTriggerProgrammaticLaunchCompletion();
#endif
}

// ============================================================
// K4: gate + w_b ielin + residual. 8 nodes/block, grid 512.
// ============================================================
#define KFN_SMEM ((4096 + 4096 + 2048 + 64 * 36) * 4)
__global__ void __launch_bounds__(256) k_fin(const float* __restrict__ feat,
                                             const float* __restrict__ wb0,
                                             const float* __restrict__ wb1,
                                             float* __restrict__ out) {
    extern __shared__ float sm[];
    float* sW0 = sm;
    float* sW1 = sm + 4096;
    float* sAg = sm + 8192;   // raw agg 8x256
    float* sAt = sm + 10240;  // gated transposed [k64][row32], stride 36
    int t = threadIdx.x;
    for (int i = t; i < 1024; i += 256) {
        ((float4*)sW0)[i] = ((const float4*)wb0)[i];
        ((float4*)sW1)[i] = ((const float4*)wb1)[i];
    }
#if __CUDA_ARCH__ >= 900
    cudaGridDependencySynchronize();   // g_agg ready past this point
#endif
    int nodeBase = blockIdx.x * 8;
    for (int i = t; i < 512; i += 256)
        ((float4*)sAg)[i] = *((const float4*)(g_agg + nodeBase * 256) + i);
    __syncthreads();
    for (int i = t; i < 512; i += 256) {
        int nl = i >> 6, c = i & 63;
        const float* a = sAg + nl * 256;
        float a0 = a[c], v1 = a[64 + c], v2 = a[128 + c], v3 = a[192 + c];
        float gt0 = ssp(a0);
        float gt1 = ssp(sqrtf(v1 * v1 + v2 * v2 + v3 * v3 + 1e-12f));
        int row = nl * 4;
        sAt[c * 36 + row] = a0 * gt0;
        sAt[c * 36 + row + 1] = v1 * gt1;
        sAt[c * 36 + row + 2] = v2 * gt1;
        sAt[c * 36 + row + 3] = v3 * gt1;
    }
    __syncthreads();
    int rg = t >> 5, c0 = (t & 31) * 2;
    u64 acc0 = pk2(0.f, 0.f), acc1 = acc0, acc2 = acc0, acc3 = acc0;
#pragma unroll 4
    for (int k = 0; k < 64; k++) {
        float4 a = *(const float4*)(sAt + k * 36 + rg * 4);
        u64 w0 = *(const u64*)(sW0 + k * 64 + c0);
        u64 w1 = *(const u64*)(sW1 + k * 64 + c0);
        acc0 = fma2_(pk2(a.x, a.x), w0, acc0);
        acc1 = fma2_(pk2(a.y, a.y), w1, acc1);
        acc2 = fma2_(pk2(a.z, a.z), w1, acc2);
        acc3 = fma2_(pk2(a.w, a.w), w1, acc3);
    }
    int node = nodeBase + rg;
    u64 av[4] = {acc0, acc1, acc2, acc3};
#pragma unroll
    for (int jj = 0; jj < 4; jj++) {
        int idx = node * 256 + jj * 64 + c0;
        float2 fv = *(const float2*)(feat + idx);
        float oa, ob;
        upk2(av[jj], oa, ob);
        *(float2*)(out + idx) = make_float2(fv.x + oa, fv.y + ob);
    }
}

// ============================================================
template <typename... Args>
static void launch_pdl(void (*kern)(Args...), int grid, int block, int smem, Args... args) {
    cudaLaunchConfig_t cfg = {};
    cfg.gridDim = dim3(grid, 1, 1);
    cfg.blockDim = dim3(block, 1, 1);
    cfg.dynamicSmemBytes = (size_t)smem;
    cfg.stream = 0;
    cudaLaunchAttribute attr[1];
    attr[0].id = cudaLaunchAttributeProgrammaticStreamSerialization;
    attr[0].val.programmaticStreamSerializationAllowed = 1;
    cfg.attrs = attr;
    cfg.numAttrs = 1;
    cudaLaunchKernelEx(&cfg, kern, args...);
}

extern "C" void kernel_launch(void* const* d_in, const int* in_sizes, int n_in,
                              void* d_out, int out_size) {
    const float* xyz = (const float*)d_in[0];
    const float* feat = (const float*)d_in[1];
    const float* wf1 = (const float*)d_in[2];
    const float* wf2 = (const float*)d_in[3];
    const float* wp0 = (const float*)d_in[4];
    const float* wp1 = (const float*)d_in[5];
    const float* wa0 = (const float*)d_in[6];
    const float* wa1 = (const float*)d_in[7];
    const float* wb0 = (const float*)d_in[8];
    const float* wb1 = (const float*)d_in[9];
    const int* src = (const int*)d_in[10];
    const int* emask = (const int*)d_in[11];
    float* out = (float*)d_out;

    cudaFuncSetAttribute(k_pre, cudaFuncAttributeMaxDynamicSharedMemorySize, KP_SMEM);
    cudaFuncSetAttribute(k_edge, cudaFuncAttributeMaxDynamicSharedMemorySize, KE_SMEM);
    cudaFuncSetAttribute(k_ag, cudaFuncAttributeMaxDynamicSharedMemorySize, KAG_SMEM);
    cudaFuncSetAttribute(k_fin, cudaFuncAttributeMaxDynamicSharedMemorySize, KFN_SMEM);

    k_pre<<<512, 256, KP_SMEM>>>(feat, wp0, wp1);
    launch_pdl(k_edge, NN / KE_WARPS, 128, KE_SMEM, xyz, wf1, wf2, src, emask);
    launch_pdl(k_ag, 512, 256, KAG_SMEM, wa0, wa1);
    launch_pdl(k_fin, 512, 256, KFN_SMEM, feat, wb0, wb1, out);
}